// round 16
// baseline (speedup 1.0000x reference)
#include <cuda_runtime.h>

// Problem constants
#define B_  4
#define T_  4096
#define C_  1024
#define D_  64
#define BT_ (B_ * T_)          // 16384 rows for projections
#define SCALE 0.03125f          // C^-0.5 = 1/32

// Scratch for projected q, k, v : [B*T, 64] each (4 MB each)
__device__ float g_q[BT_ * D_];
__device__ float g_k[BT_ * D_];
__device__ float g_v[BT_ * D_];

// float4 component access (resolves to registers under full unroll)
#define F4C(v, i) ((i) == 0 ? (v).x : ((i) == 1 ? (v).y : ((i) == 2 ? (v).z : (v).w)))

// ---------------------------------------------------------------------------
// Projection: y[m][n] = sum_c x[m][c] * w[n][c]
// x: [BT, 1024] row-major, w: [64, 1024] row-major, y: [BT, 64]
// Block: 256 threads, tile M=64 x N=64, K-chunks of 64.
// ---------------------------------------------------------------------------
__global__ __launch_bounds__(256) void proj_kernel(const float* __restrict__ x,
                                                   const float* __restrict__ w,
                                                   float* __restrict__ y) {
    __shared__ float Xs[64 * 68];   // natural [row][c], stride 68 (16B aligned)
    __shared__ float Wt[64 * 68];   // transposed [c][n], stride 68

    const int t  = threadIdx.x;
    const int ty = t >> 4;          // 0..15 -> 4 rows each
    const int tx = t & 15;          // 0..15 -> 4 cols each
    const int row0 = blockIdx.x * 64;

    float acc[4][4] = {};

    for (int kc = 0; kc < C_; kc += 64) {
        // cooperative load: X natural, W transposed
        #pragma unroll
        for (int it = 0; it < 16; ++it) {
            int idx = t + it * 256;
            int r = idx >> 6;       // 0..63
            int c = idx & 63;       // 0..63
            Xs[r * 68 + c] = x[(size_t)(row0 + r) * C_ + kc + c];
            Wt[c * 68 + r] = w[(size_t)r * C_ + kc + c];   // r is output dim n
        }
        __syncthreads();

        #pragma unroll 4
        for (int c4 = 0; c4 < 16; ++c4) {
            float4 av[4], bv[4];
            #pragma unroll
            for (int i = 0; i < 4; ++i)
                av[i] = *(const float4*)&Xs[(ty * 4 + i) * 68 + c4 * 4];
            #pragma unroll
            for (int cc = 0; cc < 4; ++cc)
                bv[cc] = *(const float4*)&Wt[(c4 * 4 + cc) * 68 + tx * 4];
            #pragma unroll
            for (int cc = 0; cc < 4; ++cc)
                #pragma unroll
                for (int i = 0; i < 4; ++i) {
                    float a = F4C(av[i], cc);
                    acc[i][0] += a * bv[cc].x;
                    acc[i][1] += a * bv[cc].y;
                    acc[i][2] += a * bv[cc].z;
                    acc[i][3] += a * bv[cc].w;
                }
        }
        __syncthreads();
    }

    #pragma unroll
    for (int i = 0; i < 4; ++i) {
        float4 r = make_float4(acc[i][0], acc[i][1], acc[i][2], acc[i][3]);
        *(float4*)&y[(size_t)(row0 + ty * 4 + i) * D_ + tx * 4] = r;
    }
}

// ---------------------------------------------------------------------------
// Causal flash attention, fp32, online softmax.
// Each block handles TWO q-tiles (j and 63-j) -> constant 65 key-tile
// iterations per block, perfect load balance across 128 blocks.
// ---------------------------------------------------------------------------
__global__ __launch_bounds__(256) void attn_kernel(float* __restrict__ out) {
    extern __shared__ float sm[];
    float* Qs = sm;                 // [64][68] natural [row][d]
    float* Kt = Qs + 64 * 68;       // [64][68] transposed [d][key]
    float* Vs = Kt + 64 * 68;       // [64][64] natural [key][v]
    float* Ps = Vs + 64 * 64;       // [64][64] natural [row][key]

    const int t  = threadIdx.x;
    const int ty = t >> 4;
    const int tx = t & 15;
    const int b  = blockIdx.y;

    const float* qg = g_q + (size_t)b * T_ * D_;
    const float* kg = g_k + (size_t)b * T_ * D_;
    const float* vg = g_v + (size_t)b * T_ * D_;

    #pragma unroll 1
    for (int half = 0; half < 2; ++half) {
        const int qt = (half == 0) ? (int)blockIdx.x : (63 - (int)blockIdx.x);

        // load Q tile (natural layout)
        #pragma unroll
        for (int it = 0; it < 16; ++it) {
            int idx = t + it * 256;
            int r = idx >> 6, d = idx & 63;
            Qs[r * 68 + d] = qg[(size_t)(qt * 64 + r) * D_ + d];
        }

        float m[4], l[4], o[4][4];
        #pragma unroll
        for (int i = 0; i < 4; ++i) {
            m[i] = -1e30f; l[i] = 0.0f;
            o[i][0] = o[i][1] = o[i][2] = o[i][3] = 0.0f;
        }

        const int nkt = qt + 1;
        for (int kt = 0; kt < nkt; ++kt) {
            // load K (transposed d-major) and V (natural)
            #pragma unroll
            for (int it = 0; it < 16; ++it) {
                int idx = t + it * 256;
                int r = idx >> 6, d = idx & 63;
                Kt[d * 68 + r] = kg[(size_t)(kt * 64 + r) * D_ + d];
                Vs[r * 64 + d] = vg[(size_t)(kt * 64 + r) * D_ + d];
            }
            __syncthreads();

            // S = Q K^T  (64x64x64)
            float s[4][4] = {};
            #pragma unroll 4
            for (int d4 = 0; d4 < 16; ++d4) {
                float4 av[4], bv[4];
                #pragma unroll
                for (int i = 0; i < 4; ++i)
                    av[i] = *(const float4*)&Qs[(ty * 4 + i) * 68 + d4 * 4];
                #pragma unroll
                for (int dd = 0; dd < 4; ++dd)
                    bv[dd] = *(const float4*)&Kt[(d4 * 4 + dd) * 68 + tx * 4];
                #pragma unroll
                for (int dd = 0; dd < 4; ++dd)
                    #pragma unroll
                    for (int i = 0; i < 4; ++i) {
                        float a = F4C(av[i], dd);
                        s[i][0] += a * bv[dd].x;
                        s[i][1] += a * bv[dd].y;
                        s[i][2] += a * bv[dd].z;
                        s[i][3] += a * bv[dd].w;
                    }
            }

            // scale + causal mask (diagonal tile only)
            const bool diag = (kt == qt);
            #pragma unroll
            for (int i = 0; i < 4; ++i)
                #pragma unroll
                for (int j = 0; j < 4; ++j) {
                    float v = s[i][j] * SCALE;
                    if (diag && (tx * 4 + j > ty * 4 + i)) v = -1e30f;
                    s[i][j] = v;
                }

            // online softmax update
            #pragma unroll
            for (int i = 0; i < 4; ++i) {
                float mt = fmaxf(fmaxf(s[i][0], s[i][1]), fmaxf(s[i][2], s[i][3]));
                #pragma unroll
                for (int off = 1; off < 16; off <<= 1)
                    mt = fmaxf(mt, __shfl_xor_sync(0xffffffffu, mt, off));
                float mnew = fmaxf(m[i], mt);
                float alpha = __expf(m[i] - mnew);
                float rs = 0.0f;
                #pragma unroll
                for (int j = 0; j < 4; ++j) {
                    float p = __expf(s[i][j] - mnew);
                    s[i][j] = p;
                    rs += p;
                }
                #pragma unroll
                for (int off = 1; off < 16; off <<= 1)
                    rs += __shfl_xor_sync(0xffffffffu, rs, off);
                l[i] = l[i] * alpha + rs;
                m[i] = mnew;
                o[i][0] *= alpha; o[i][1] *= alpha; o[i][2] *= alpha; o[i][3] *= alpha;
            }

            // store P (natural [row][key], conflict-free float4)
            #pragma unroll
            for (int i = 0; i < 4; ++i) {
                float4 r = make_float4(s[i][0], s[i][1], s[i][2], s[i][3]);
                *(float4*)&Ps[(ty * 4 + i) * 64 + tx * 4] = r;
            }
            __syncthreads();

            // O += P V   (64x64x64)
            #pragma unroll 4
            for (int k4 = 0; k4 < 16; ++k4) {
                float4 pv[4], vv[4];
                #pragma unroll
                for (int i = 0; i < 4; ++i)
                    pv[i] = *(const float4*)&Ps[(ty * 4 + i) * 64 + k4 * 4];
                #pragma unroll
                for (int kk = 0; kk < 4; ++kk)
                    vv[kk] = *(const float4*)&Vs[(k4 * 4 + kk) * 64 + tx * 4];
                #pragma unroll
                for (int kk = 0; kk < 4; ++kk)
                    #pragma unroll
                    for (int i = 0; i < 4; ++i) {
                        float p = F4C(pv[i], kk);
                        o[i][0] += p * vv[kk].x;
                        o[i][1] += p * vv[kk].y;
                        o[i][2] += p * vv[kk].z;
                        o[i][3] += p * vv[kk].w;
                    }
            }
            __syncthreads();
        }

        // write normalized output
        #pragma unroll
        for (int i = 0; i < 4; ++i) {
            float inv = 1.0f / l[i];
            float4 r = make_float4(o[i][0] * inv, o[i][1] * inv,
                                   o[i][2] * inv, o[i][3] * inv);
            size_t row = (size_t)b * T_ + (size_t)qt * 64 + ty * 4 + i;
            *(float4*)&out[row * D_ + tx * 4] = r;
        }
        __syncthreads();   // Qs reload guard for second half
    }
}

// ---------------------------------------------------------------------------
// kernel_launch
// ---------------------------------------------------------------------------
extern "C" void kernel_launch(void* const* d_in, const int* in_sizes, int n_in,
                              void* d_out, int out_size) {
    const float* q_embs = (const float*)d_in[0];
    const float* k_embs = (const float*)d_in[1];
    const float* v_embs = (const float*)d_in[2];
    const float* w_q    = (const float*)d_in[3];
    const float* w_k    = (const float*)d_in[4];
    const float* w_v    = (const float*)d_in[5];
    float* out = (float*)d_out;

    float *gq, *gk, *gv;
    cudaGetSymbolAddress((void**)&gq, g_q);
    cudaGetSymbolAddress((void**)&gk, g_k);
    cudaGetSymbolAddress((void**)&gv, g_v);

    // Projections: 3 launches of the same tiled GEMM
    dim3 pgrid(BT_ / 64);
    proj_kernel<<<pgrid, 256>>>(q_embs, w_q, gq);
    proj_kernel<<<pgrid, 256>>>(k_embs, w_k, gk);
    proj_kernel<<<pgrid, 256>>>(v_embs, w_v, gv);

    // Attention: dynamic smem = (2*68 + 2*64) * 64 * 4 = 67584 B
    const int smem = (2 * 68 + 2 * 64) * 64 * 4;
    cudaFuncSetAttribute(attn_kernel, cudaFuncAttributeMaxDynamicSharedMemorySize, smem);
    dim3 agrid(32, B_);   // 32 q-tile PAIRS per batch -> 128 balanced blocks
    attn_kernel<<<agrid, 256, smem>>>(out);
}